// round 4
// baseline (speedup 1.0000x reference)
#include <cuda_runtime.h>
#include <cstdint>
#include <cstddef>

// ---------------- problem constants ----------------
#define Bn   4
#define Cc   128
#define Hh   128
#define Wd   256
#define HW   (Hh*Wd)          // 32768
#define Ff   128
#define CVC  49
#define RAD  24
#define NPIX (Bn*HW)          // 131072
static const size_t NC_ = (size_t)Bn * CVC * HW;  // elements per corr-like tensor

// ---------------- device scratch (static, no allocation) ----------------
__device__ float g_f1n[(size_t)NPIX * Ff];   // [B][F][H][W]
__device__ float g_f2n[(size_t)NPIX * Ff];
__device__ float g_Wt1[Cc * Ff];             // W transposed: [c][o]
__device__ float g_Wt2[Cc * Ff];
__device__ float g_M[9 * CVC];               // [i][j][c], i=volume, j=logit
__device__ float g_beta[3];

// ---------------- helpers ----------------
__device__ __forceinline__ unsigned long long bcast2(float v) {
    unsigned long long r; asm("mov.b64 %0, {%1,%1};" : "=l"(r) : "f"(v)); return r;
}
__device__ __forceinline__ void unpack2(unsigned long long p, float& lo, float& hi) {
    asm("mov.b64 {%0,%1}, %2;" : "=f"(lo), "=f"(hi) : "l"(p));
}
__device__ __forceinline__ void ffma2(unsigned long long& acc, unsigned long long a, unsigned long long b) {
    asm("fma.rn.f32x2 %0, %1, %2, %0;" : "+l"(acc) : "l"(a), "l"(b));
}
__device__ __forceinline__ void cp16(void* smem_dst, const void* gmem_src) {
    unsigned int s = (unsigned int)__cvta_generic_to_shared(smem_dst);
    asm volatile("cp.async.cg.shared.global [%0], [%1], 16;" :: "r"(s), "l"(gmem_src));
}
__device__ __forceinline__ void cp_commit() { asm volatile("cp.async.commit_group;"); }
template <int N>
__device__ __forceinline__ void cp_wait() { asm volatile("cp.async.wait_group %0;" :: "n"(N)); }

// ---------------- prep: transpose weights + fold selector ----------------
__global__ void prep_kernel(const float* __restrict__ Wf1, const float* __restrict__ Wf2,
                            const float* __restrict__ Wgeo, const float* __restrict__ bgeo,
                            const float* __restrict__ Wsel, const float* __restrict__ bsel)
{
    int t = threadIdx.x;
    for (int idx = t; idx < Cc * Ff; idx += blockDim.x) {
        int o = idx / Cc, c = idx % Cc;          // W layout [o][c]
        g_Wt1[c * Ff + o] = Wf1[idx];
        g_Wt2[c * Ff + o] = Wf2[idx];
    }
    for (int idx = t; idx < 9 * CVC; idx += blockDim.x) {
        int i = idx / (3 * CVC);
        int r = idx % (3 * CVC);
        int j = r / CVC;
        int c = r % CVC;
        float s = 0.f;
        for (int m = 0; m < 96; m++)
            s += Wsel[j * 288 + i * 96 + m] * Wgeo[m * CVC + c];
        g_M[idx] = s;
    }
    if (t < 3) {
        float s = bsel[t];
        for (int q = 0; q < 288; q++)
            s += Wsel[t * 288 + q] * bgeo[q % 96];
        g_beta[t] = s;
    }
}

// ---------------- fmap: conv1x1 GEMM + L2-normalize, cp.async double-buffered ----------------
#define FMP 128
#define FMK 32
#define FEAT_STRIDE 132

extern __shared__ float dynsm[];

__global__ __launch_bounds__(256) void fmap_kernel(
    const float* __restrict__ featA, const float* __restrict__ featB,
    const float* __restrict__ biasA, const float* __restrict__ biasB)
{
    // dynamic smem: featS[2][32][132], wS[2][32][128], ssS[128]
    float* featS0 = dynsm;
    float* featS1 = dynsm + FMK * FEAT_STRIDE;
    float* wS0    = dynsm + 2 * FMK * FEAT_STRIDE;
    float* wS1    = wS0 + FMK * Ff;
    float* ssS    = wS1 + FMK * Ff;
    float* featB_[2] = {featS0, featS1};
    float* wB_[2]    = {wS0, wS1};

    int which = blockIdx.y;
    const float* feat = which ? featB : featA;
    const float* bias = which ? biasB : biasA;
    const float* Wt   = which ? g_Wt2 : g_Wt1;
    float*       outp = which ? g_f2n : g_f1n;

    int t   = threadIdx.x;
    int p0  = blockIdx.x * FMP;
    int b   = p0 / HW;
    int rem = p0 % HW;
    const float* fbase = feat + (size_t)b * Cc * HW + rem;

    int pg  = t & 15,  og = t >> 4;
    int px0 = pg * 8,  o0 = og * 8;

    if (t < FMP) ssS[t] = 0.f;

    unsigned long long acc[8][4];
    #pragma unroll
    for (int i = 0; i < 8; i++)
        #pragma unroll
        for (int j = 0; j < 4; j++) acc[i][j] = 0ULL;

    // async tile loaders: 1024 float4 each for feat and W, 256 threads -> 4+4 cp16/thread
    auto load_tile = [&](int c0, int s) {
        #pragma unroll
        for (int it = 0; it < 4; it++) {
            int idx = t + it * 256;
            int kc = idx >> 5, q = idx & 31;
            cp16(&featB_[s][kc * FEAT_STRIDE + q * 4],
                 &fbase[(size_t)(c0 + kc) * HW + q * 4]);
        }
        #pragma unroll
        for (int it = 0; it < 4; it++) {
            int idx = t + it * 256;
            int kc = idx >> 5, q = idx & 31;
            cp16(&wB_[s][kc * Ff + q * 4], &Wt[(c0 + kc) * Ff + q * 4]);
        }
        cp_commit();
    };

    load_tile(0, 0);

    #pragma unroll
    for (int i = 0; i < Cc / FMK; i++) {
        if (i + 1 < Cc / FMK) { load_tile((i + 1) * FMK, (i + 1) & 1); cp_wait<1>(); }
        else                  { cp_wait<0>(); }
        __syncthreads();

        const float* fS = featB_[i & 1];
        const float* wS = wB_[i & 1];
        #pragma unroll
        for (int kk = 0; kk < FMK; kk++) {
            ulonglong2 f01 = *(const ulonglong2*)&fS[kk * FEAT_STRIDE + px0];
            ulonglong2 f23 = *(const ulonglong2*)&fS[kk * FEAT_STRIDE + px0 + 4];
            float4 w0 = *(const float4*)&wS[kk * Ff + o0];
            float4 w1 = *(const float4*)&wS[kk * Ff + o0 + 4];
            float wv[8] = {w0.x, w0.y, w0.z, w0.w, w1.x, w1.y, w1.z, w1.w};
            #pragma unroll
            for (int oi = 0; oi < 8; oi++) {
                unsigned long long ww = bcast2(wv[oi]);
                ffma2(acc[oi][0], ww, f01.x);
                ffma2(acc[oi][1], ww, f01.y);
                ffma2(acc[oi][2], ww, f23.x);
                ffma2(acc[oi][3], ww, f23.y);
            }
        }
        __syncthreads();
    }

    float bia[8];
    #pragma unroll
    for (int oi = 0; oi < 8; oi++) bia[oi] = bias[o0 + oi];

    float ss[8];
    #pragma unroll
    for (int pp = 0; pp < 8; pp++) ss[pp] = 0.f;
    #pragma unroll
    for (int oi = 0; oi < 8; oi++)
        #pragma unroll
        for (int p = 0; p < 4; p++) {
            float lo, hi; unpack2(acc[oi][p], lo, hi);
            lo += bia[oi]; hi += bia[oi];
            ss[2 * p]     += lo * lo;
            ss[2 * p + 1] += hi * hi;
        }
    #pragma unroll
    for (int pp = 0; pp < 8; pp++) atomicAdd(&ssS[px0 + pp], ss[pp]);
    __syncthreads();

    float inv[8];
    #pragma unroll
    for (int pp = 0; pp < 8; pp++) inv[pp] = 1.f / (sqrtf(ssS[px0 + pp]) + 1e-8f);

    #pragma unroll
    for (int oi = 0; oi < 8; oi++) {
        float v[8];
        #pragma unroll
        for (int p = 0; p < 4; p++) {
            float lo, hi; unpack2(acc[oi][p], lo, hi);
            v[2 * p]     = (lo + bia[oi]) * inv[2 * p];
            v[2 * p + 1] = (hi + bia[oi]) * inv[2 * p + 1];
        }
        float* op = outp + ((size_t)b * Ff + o0 + oi) * HW + rem + px0;
        *(float4*)op       = make_float4(v[0], v[1], v[2], v[3]);
        *(float4*)(op + 4) = make_float4(v[4], v[5], v[6], v[7]);
    }
}

// ---------------- fused correlation + selector ----------------
// block: 64 x of one (b,h) row. Phase 1: banded Gram (as R3). Phase 2: stage corr
// tile in smem. Phase 3: load cv tiles once. Phase 4: folded logits + softmax.
// Phase 5: final = corr + w·cv, write final + init_corr + w. No DRAM round-trips.
__global__ __launch_bounds__(224) void corrsel_kernel(const float* __restrict__ cv0,
                                                      const float* __restrict__ cv1,
                                                      const float* __restrict__ cv2,
                                                      float* __restrict__ out)
{
    // dynamic smem layout (floats):
    //   s1c : 64*68   = 4352   (f1 tile; reused as outS 49*64=3136)
    //   cvS : 3*49*64 = 9408   (first 64*116=7424 reused as s2c during phase 1)
    //   wsm : 3*64    = 192
    float* s1c = dynsm;
    float* cvS = dynsm + 64 * 68;
    float* s2c = cvS;
    float* wsm = cvS + 3 * CVC * 64;
    float* outS = s1c;

    int t   = threadIdx.x;
    int blk = blockIdx.x;
    int bh  = blk >> 2;
    int x0  = (blk & 3) * 64;
    int b   = bh / Hh, h = bh % Hh;

    const float* f1 = g_f1n + (size_t)b * Ff * HW + (size_t)h * Wd;
    const float* f2 = g_f2n + (size_t)b * Ff * HW + (size_t)h * Wd;

    int xt = t & 15, j = t >> 4;       // j 0..13 (j==13 -> load-only helper)
    bool active = (j < 13);

    unsigned long long acc[4][2];
    #pragma unroll
    for (int i = 0; i < 4; i++) { acc[i][0] = 0ULL; acc[i][1] = 0ULL; }

    // ---- phase 1: banded Gram over 2 channel halves ----
    for (int half = 0; half < 2; half++) {
        __syncthreads();
        int cbase = half * 64;
        for (int idx = t; idx < 1024; idx += 224) {        // 64 ch x 16 float4
            int o = idx >> 4, q = idx & 15;
            *(float4*)&s1c[o * 68 + q * 4] =
                *(const float4*)&f1[(size_t)(cbase + o) * HW + x0 + q * 4];
        }
        for (int idx = t; idx < 1792; idx += 224) {        // 64 ch x 28 float4
            int o = idx / 28, q = idx - o * 28;
            int xg = x0 - RAD + q * 4;                     // OOB always whole-float4
            float4 vv = make_float4(0.f, 0.f, 0.f, 0.f);
            if (xg >= 0 && xg <= Wd - 4)
                vv = *(const float4*)&f2[(size_t)(cbase + o) * HW + xg];
            *(float4*)&s2c[o * 116 + q * 4] = vv;
        }
        __syncthreads();

        if (active) {
            #pragma unroll 4
            for (int o = 0; o < 64; o++) {
                float4 a = *(const float4*)&s1c[o * 68 + 4 * xt];
                ulonglong2 bb = *(const ulonglong2*)&s2c[o * 116 + 4 * (xt + j)];
                float av[4] = {a.x, a.y, a.z, a.w};
                #pragma unroll
                for (int i = 0; i < 4; i++) {
                    unsigned long long aa = bcast2(av[i]);
                    ffma2(acc[i][0], aa, bb.x);
                    ffma2(acc[i][1], aa, bb.y);
                }
            }
        }
    }

    __syncthreads();   // phase-1 reads of s1c/s2c done

    // ---- phase 2: stage corr tile;  phase 3: load cv tiles (overlapped) ----
    if (active) {
        #pragma unroll
        for (int i = 0; i < 4; i++) {
            float vals[4];
            unpack2(acc[i][0], vals[0], vals[1]);
            unpack2(acc[i][1], vals[2], vals[3]);
            #pragma unroll
            for (int ip = 0; ip < 4; ip++) {
                int k = 48 - 4 * j + i - ip;
                if (k >= 0 && k <= 48)
                    outS[k * 64 + 4 * xt + i] = vals[ip];
            }
        }
    }
    {
        size_t gbase = ((size_t)b * CVC * Hh + h) * Wd + x0;   // + c*HW*... careful below
        for (int idx = t; idx < 3 * CVC * 16; idx += 224) {    // 2352 float4
            int v = idx / (CVC * 16);
            int r = idx - v * (CVC * 16);
            int c = r >> 4, q = r & 15;
            const float* src = (v == 0 ? cv0 : (v == 1 ? cv1 : cv2));
            *(float4*)&cvS[(v * CVC + c) * 64 + q * 4] =
                *(const float4*)&src[((size_t)(b * CVC + c) * Hh + h) * Wd + x0 + q * 4];
        }
        (void)gbase;
    }
    __syncthreads();

    // ---- phase 4: folded logits + softmax (threads 0..63, one pixel each) ----
    if (t < 64) {
        float l0 = g_beta[0], l1 = g_beta[1], l2 = g_beta[2];
        #pragma unroll 7
        for (int c = 0; c < CVC; c++) {
            float v0 = cvS[(0 * CVC + c) * 64 + t];
            float v1 = cvS[(1 * CVC + c) * 64 + t];
            float v2 = cvS[(2 * CVC + c) * 64 + t];
            l0 = fmaf(g_M[0 * CVC + c], v0, fmaf(g_M[147 + 0 * CVC + c], v1, fmaf(g_M[294 + 0 * CVC + c], v2, l0)));
            l1 = fmaf(g_M[1 * CVC + c], v0, fmaf(g_M[147 + 1 * CVC + c], v1, fmaf(g_M[294 + 1 * CVC + c], v2, l1)));
            l2 = fmaf(g_M[2 * CVC + c], v0, fmaf(g_M[147 + 2 * CVC + c], v1, fmaf(g_M[294 + 2 * CVC + c], v2, l2)));
        }
        float m  = fmaxf(l0, fmaxf(l1, l2));
        float e0 = expf(l0 - m), e1 = expf(l1 - m), e2 = expf(l2 - m);
        float inv = 1.f / (e0 + e1 + e2);
        float w0 = e0 * inv, w1 = e1 * inv, w2 = e2 * inv;
        wsm[0 * 64 + t] = w0;
        wsm[1 * 64 + t] = w1;
        wsm[2 * 64 + t] = w2;
        float* wout = out + 2 * NC_ + ((size_t)b * 3 * Hh + h) * Wd + x0 + t;
        wout[0]               = w0;
        wout[(size_t)HW]      = w1;
        wout[(size_t)2 * HW]  = w2;
    }
    __syncthreads();

    // ---- phase 5: final = corr + w·cv ; write final + init_corr ----
    for (int idx = t; idx < CVC * 16; idx += 224) {        // 784 float4
        int k = idx >> 4, q = idx & 15;
        float4 corr4 = *(const float4*)&outS[k * 64 + q * 4];
        float4 a0 = *(const float4*)&cvS[(0 * CVC + k) * 64 + q * 4];
        float4 a1 = *(const float4*)&cvS[(1 * CVC + k) * 64 + q * 4];
        float4 a2 = *(const float4*)&cvS[(2 * CVC + k) * 64 + q * 4];
        float4 w0 = *(const float4*)&wsm[0 * 64 + q * 4];
        float4 w1 = *(const float4*)&wsm[1 * 64 + q * 4];
        float4 w2 = *(const float4*)&wsm[2 * 64 + q * 4];
        float4 fin;
        fin.x = corr4.x + fmaf(w0.x, a0.x, fmaf(w1.x, a1.x, w2.x * a2.x));
        fin.y = corr4.y + fmaf(w0.y, a0.y, fmaf(w1.y, a1.y, w2.y * a2.y));
        fin.z = corr4.z + fmaf(w0.z, a0.z, fmaf(w1.z, a1.z, w2.z * a2.z));
        fin.w = corr4.w + fmaf(w0.w, a0.w, fmaf(w1.w, a1.w, w2.w * a2.w));
        size_t off = ((size_t)(b * CVC + k) * Hh + h) * Wd + x0 + q * 4;
        *(float4*)&out[off]       = fin;
        *(float4*)&out[NC_ + off] = corr4;
    }
}

// ---------------- launch ----------------
extern "C" void kernel_launch(void* const* d_in, const int* in_sizes, int n_in,
                              void* d_out, int out_size)
{
    const float* feat_l1 = (const float*)d_in[0];
    const float* feat_r1 = (const float*)d_in[1];
    const float* cv0     = (const float*)d_in[2];
    const float* cv1     = (const float*)d_in[3];
    const float* cv2     = (const float*)d_in[4];
    const float* W_f1    = (const float*)d_in[5];
    const float* b_f1    = (const float*)d_in[6];
    const float* W_f2    = (const float*)d_in[7];
    const float* b_f2    = (const float*)d_in[8];
    const float* W_geo   = (const float*)d_in[9];
    const float* b_geo   = (const float*)d_in[10];
    const float* W_sel   = (const float*)d_in[11];
    const float* b_sel   = (const float*)d_in[12];
    float* out = (float*)d_out;

    prep_kernel<<<1, 256>>>(W_f1, W_f2, W_geo, b_geo, W_sel, b_sel);

    int fm_smem = (2 * FMK * FEAT_STRIDE + 2 * FMK * Ff + FMP) * (int)sizeof(float); // ~67KB
    static int fm_set = 0;
    if (!fm_set) {
        cudaFuncSetAttribute(fmap_kernel, cudaFuncAttributeMaxDynamicSharedMemorySize, fm_smem);
        fm_set = 1;
    }
    fmap_kernel<<<dim3(NPIX / FMP, 2), 256, fm_smem>>>(feat_l1, feat_r1, b_f1, b_f2);

    int cs_smem = (64 * 68 + 3 * CVC * 64 + 3 * 64) * (int)sizeof(float);            // ~55.8KB
    static int cs_set = 0;
    if (!cs_set) {
        cudaFuncSetAttribute(corrsel_kernel, cudaFuncAttributeMaxDynamicSharedMemorySize, cs_smem);
        cs_set = 1;
    }
    corrsel_kernel<<<Bn * Hh * (Wd / 64), 224, cs_smem>>>(cv0, cv1, cv2, out);
}

// round 5
// speedup vs baseline: 1.0498x; 1.0498x over previous
#include <cuda_runtime.h>
#include <cstdint>
#include <cstddef>

// ---------------- problem constants ----------------
#define Bn   4
#define Cc   128
#define Hh   128
#define Wd   256
#define HW   (Hh*Wd)          // 32768
#define Ff   128
#define CVC  49
#define RAD  24
#define NPIX (Bn*HW)          // 131072
static const size_t NC_ = (size_t)Bn * CVC * HW;  // elements per corr-like tensor

// ---------------- device scratch (static, no allocation) ----------------
__device__ float g_f1n[(size_t)NPIX * Ff];   // [B][F][H][W]
__device__ float g_f2n[(size_t)NPIX * Ff];
__device__ float g_Wt1[Cc * Ff];             // W transposed: [c][o]
__device__ float g_Wt2[Cc * Ff];
__device__ float g_M[9 * CVC];               // [i][j][c], i=volume, j=logit
__device__ float g_beta[3];

// ---------------- helpers ----------------
__device__ __forceinline__ unsigned long long bcast2(float v) {
    unsigned long long r; asm("mov.b64 %0, {%1,%1};" : "=l"(r) : "f"(v)); return r;
}
__device__ __forceinline__ void unpack2(unsigned long long p, float& lo, float& hi) {
    asm("mov.b64 {%0,%1}, %2;" : "=f"(lo), "=f"(hi) : "l"(p));
}
__device__ __forceinline__ void ffma2(unsigned long long& acc, unsigned long long a, unsigned long long b) {
    asm("fma.rn.f32x2 %0, %1, %2, %0;" : "+l"(acc) : "l"(a), "l"(b));
}

// ---------------- prep: parallel transpose + selector fold ----------------
// blocks 0..63: weight transpose stripes; 64..66: M rows per volume i; 67: beta.
__global__ void prep_kernel(const float* __restrict__ Wf1, const float* __restrict__ Wf2,
                            const float* __restrict__ Wgeo, const float* __restrict__ bgeo,
                            const float* __restrict__ Wsel, const float* __restrict__ bsel)
{
    int blk = blockIdx.x, t = threadIdx.x;
    if (blk < 64) {
        int base = blk * 256;                       // 64 blocks x 256 = 16384
        int idx = base + t;
        if (idx < Cc * Ff) {
            int o = idx / Cc, c = idx % Cc;         // W layout [o][c]
            g_Wt1[c * Ff + o] = Wf1[idx];
            g_Wt2[c * Ff + o] = Wf2[idx];
        }
    } else if (blk < 67) {
        int i = blk - 64;                            // volume index
        for (int r = t; r < 3 * CVC; r += 256) {     // j*CVC + c
            int j = r / CVC, c = r % CVC;
            float s = 0.f;
            #pragma unroll 8
            for (int m = 0; m < 96; m++)
                s += Wsel[j * 288 + i * 96 + m] * Wgeo[m * CVC + c];
            g_M[i * 3 * CVC + j * CVC + c] = s;
        }
    } else {
        if (t < 3) {
            float s = bsel[t];
            for (int q = 0; q < 288; q++)
                s += Wsel[t * 288 + q] * bgeo[q % 96];
            g_beta[t] = s;
        }
    }
}

// ---------------- fmap: conv1x1 (GEMM) + channel L2-normalize (R3 sync form) ----------------
#define FMP 128
#define FMK 32

__global__ __launch_bounds__(256) void fmap_kernel(
    const float* __restrict__ featA, const float* __restrict__ featB,
    const float* __restrict__ biasA, const float* __restrict__ biasB)
{
    __shared__ float featS[FMK][132];   // padded rows
    __shared__ float wS[FMK][Ff];
    __shared__ float ssS[FMP];

    int which = blockIdx.y;
    const float* feat = which ? featB : featA;
    const float* bias = which ? biasB : biasA;
    const float* Wt   = which ? g_Wt2 : g_Wt1;
    float*       outp = which ? g_f2n : g_f1n;

    int t   = threadIdx.x;
    int p0  = blockIdx.x * FMP;
    int b   = p0 / HW;
    int rem = p0 % HW;
    const float* fbase = feat + (size_t)b * Cc * HW + rem;

    int pg  = t & 15,  og = t >> 4;
    int px0 = pg * 8,  o0 = og * 8;

    if (t < FMP) ssS[t] = 0.f;

    unsigned long long acc[8][4];
    #pragma unroll
    for (int i = 0; i < 8; i++)
        #pragma unroll
        for (int j = 0; j < 4; j++) acc[i][j] = 0ULL;

    for (int c0 = 0; c0 < Cc; c0 += FMK) {
        __syncthreads();
        #pragma unroll
        for (int it = 0; it < 4; it++) {
            int idx = t + it * 256;
            int kc = idx >> 5, q = idx & 31;
            *(float4*)&featS[kc][q * 4] =
                *(const float4*)&fbase[(size_t)(c0 + kc) * HW + q * 4];
        }
        #pragma unroll
        for (int it = 0; it < 4; it++) {
            int idx = t + it * 256;
            int kc = idx >> 5, q = idx & 31;
            *(float4*)&wS[kc][q * 4] = *(const float4*)&Wt[(c0 + kc) * Ff + q * 4];
        }
        __syncthreads();

        #pragma unroll
        for (int kk = 0; kk < FMK; kk++) {
            ulonglong2 f01 = *(const ulonglong2*)&featS[kk][px0];
            ulonglong2 f23 = *(const ulonglong2*)&featS[kk][px0 + 4];
            float4 w0 = *(const float4*)&wS[kk][o0];
            float4 w1 = *(const float4*)&wS[kk][o0 + 4];
            float wv[8] = {w0.x, w0.y, w0.z, w0.w, w1.x, w1.y, w1.z, w1.w};
            #pragma unroll
            for (int oi = 0; oi < 8; oi++) {
                unsigned long long ww = bcast2(wv[oi]);
                ffma2(acc[oi][0], ww, f01.x);
                ffma2(acc[oi][1], ww, f01.y);
                ffma2(acc[oi][2], ww, f23.x);
                ffma2(acc[oi][3], ww, f23.y);
            }
        }
    }

    float bia[8];
    #pragma unroll
    for (int oi = 0; oi < 8; oi++) bia[oi] = bias[o0 + oi];

    float ss[8];
    #pragma unroll
    for (int pp = 0; pp < 8; pp++) ss[pp] = 0.f;
    #pragma unroll
    for (int oi = 0; oi < 8; oi++)
        #pragma unroll
        for (int p = 0; p < 4; p++) {
            float lo, hi; unpack2(acc[oi][p], lo, hi);
            lo += bia[oi]; hi += bia[oi];
            ss[2 * p]     += lo * lo;
            ss[2 * p + 1] += hi * hi;
        }
    #pragma unroll
    for (int pp = 0; pp < 8; pp++) atomicAdd(&ssS[px0 + pp], ss[pp]);
    __syncthreads();

    float inv[8];
    #pragma unroll
    for (int pp = 0; pp < 8; pp++) inv[pp] = 1.f / (sqrtf(ssS[px0 + pp]) + 1e-8f);

    #pragma unroll
    for (int oi = 0; oi < 8; oi++) {
        float v[8];
        #pragma unroll
        for (int p = 0; p < 4; p++) {
            float lo, hi; unpack2(acc[oi][p], lo, hi);
            v[2 * p]     = (lo + bia[oi]) * inv[2 * p];
            v[2 * p + 1] = (hi + bia[oi]) * inv[2 * p + 1];
        }
        float* op = outp + ((size_t)b * Ff + o0 + oi) * HW + rem + px0;
        *(float4*)op       = make_float4(v[0], v[1], v[2], v[3]);
        *(float4*)(op + 4) = make_float4(v[4], v[5], v[6], v[7]);
    }
}

// ---------------- fused correlation + selector ----------------
extern __shared__ float dynsm[];
__global__ __launch_bounds__(224) void corrsel_kernel(const float* __restrict__ cv0,
                                                      const float* __restrict__ cv1,
                                                      const float* __restrict__ cv2,
                                                      float* __restrict__ out)
{
    // dynamic smem layout (floats):
    //   s1c : 64*68   = 4352   (f1 tile; tail reused: outS 49*64=3136, Msm 441+3)
    //   cvS : 3*49*64 = 9408   (first 64*116=7424 reused as s2c during phase 1)
    //   wsm : 3*64    = 192    (logits, then weights)
    float* s1c  = dynsm;
    float* cvS  = dynsm + 64 * 68;
    float* s2c  = cvS;
    float* wsm  = cvS + 3 * CVC * 64;
    float* outS = s1c;                 // [0 .. 3136)
    float* Msm  = s1c + 3136;          // [3136 .. 3577)
    float* betaS= s1c + 3136 + 441;    // 3 floats (s1c has 4352 total)

    int t   = threadIdx.x;
    int blk = blockIdx.x;
    int bh  = blk >> 2;
    int x0  = (blk & 3) * 64;
    int b   = bh / Hh, h = bh % Hh;

    const float* f1 = g_f1n + (size_t)b * Ff * HW + (size_t)h * Wd;
    const float* f2 = g_f2n + (size_t)b * Ff * HW + (size_t)h * Wd;

    int xt = t & 15, j = t >> 4;       // j 0..13 (j==13 -> load-only helper)
    bool active = (j < 13);

    unsigned long long acc[4][2];
    #pragma unroll
    for (int i = 0; i < 4; i++) { acc[i][0] = 0ULL; acc[i][1] = 0ULL; }

    // ---- phase 1: banded Gram over 2 channel halves ----
    for (int half = 0; half < 2; half++) {
        __syncthreads();
        int cbase = half * 64;
        for (int idx = t; idx < 1024; idx += 224) {        // 64 ch x 16 float4
            int o = idx >> 4, q = idx & 15;
            *(float4*)&s1c[o * 68 + q * 4] =
                *(const float4*)&f1[(size_t)(cbase + o) * HW + x0 + q * 4];
        }
        for (int idx = t; idx < 1792; idx += 224) {        // 64 ch x 28 float4
            int o = idx / 28, q = idx - o * 28;
            int xg = x0 - RAD + q * 4;                     // OOB always whole-float4
            float4 vv = make_float4(0.f, 0.f, 0.f, 0.f);
            if (xg >= 0 && xg <= Wd - 4)
                vv = *(const float4*)&f2[(size_t)(cbase + o) * HW + xg];
            *(float4*)&s2c[o * 116 + q * 4] = vv;
        }
        __syncthreads();

        if (active) {
            #pragma unroll 4
            for (int o = 0; o < 64; o++) {
                float4 a = *(const float4*)&s1c[o * 68 + 4 * xt];
                ulonglong2 bb = *(const ulonglong2*)&s2c[o * 116 + 4 * (xt + j)];
                float av[4] = {a.x, a.y, a.z, a.w};
                #pragma unroll
                for (int i = 0; i < 4; i++) {
                    unsigned long long aa = bcast2(av[i]);
                    ffma2(acc[i][0], aa, bb.x);
                    ffma2(acc[i][1], aa, bb.y);
                }
            }
        }
    }

    __syncthreads();   // phase-1 reads of s1c/s2c done

    // ---- phase 2: stage corr tile; phase 3: cv tiles + M/beta (same barrier) ----
    if (active) {
        #pragma unroll
        for (int i = 0; i < 4; i++) {
            float vals[4];
            unpack2(acc[i][0], vals[0], vals[1]);
            unpack2(acc[i][1], vals[2], vals[3]);
            #pragma unroll
            for (int ip = 0; ip < 4; ip++) {
                int k = 48 - 4 * j + i - ip;
                if (k >= 0 && k <= 48)
                    outS[k * 64 + 4 * xt + i] = vals[ip];
            }
        }
    }
    for (int idx = t; idx < 3 * CVC * 16; idx += 224) {    // 2352 float4
        int v = idx / (CVC * 16);
        int r = idx - v * (CVC * 16);
        int c = r >> 4, q = r & 15;
        const float* src = (v == 0 ? cv0 : (v == 1 ? cv1 : cv2));
        *(float4*)&cvS[(v * CVC + c) * 64 + q * 4] =
            *(const float4*)&src[((size_t)(b * CVC + c) * Hh + h) * Wd + x0 + q * 4];
    }
    for (int i = t; i < 9 * CVC; i += 224) Msm[i] = g_M[i];
    if (t < 3) betaS[t] = g_beta[t];
    __syncthreads();

    // ---- phase 4: folded logits (192 threads: 3 logits x 64 px) ----
    if (t < 192) {
        int j2 = t >> 6;         // logit 0..2
        int x  = t & 63;
        float l = betaS[j2];
        const float* M0 = Msm + 0 * 3 * CVC + j2 * CVC;
        const float* M1 = Msm + 1 * 3 * CVC + j2 * CVC;
        const float* M2 = Msm + 2 * 3 * CVC + j2 * CVC;
        #pragma unroll 7
        for (int c = 0; c < CVC; c++) {
            l = fmaf(M0[c], cvS[(0 * CVC + c) * 64 + x],
                fmaf(M1[c], cvS[(1 * CVC + c) * 64 + x],
                fmaf(M2[c], cvS[(2 * CVC + c) * 64 + x], l)));
        }
        wsm[j2 * 64 + x] = l;
    }
    __syncthreads();

    // ---- phase 4b: softmax (64 threads, thread-local slots) ----
    if (t < 64) {
        float l0 = wsm[t], l1 = wsm[64 + t], l2 = wsm[128 + t];
        float m  = fmaxf(l0, fmaxf(l1, l2));
        float e0 = expf(l0 - m), e1 = expf(l1 - m), e2 = expf(l2 - m);
        float inv = 1.f / (e0 + e1 + e2);
        float w0 = e0 * inv, w1 = e1 * inv, w2 = e2 * inv;
        wsm[t] = w0; wsm[64 + t] = w1; wsm[128 + t] = w2;
        float* wout = out + 2 * NC_ + ((size_t)b * 3 * Hh + h) * Wd + x0 + t;
        wout[0]              = w0;
        wout[(size_t)HW]     = w1;
        wout[(size_t)2 * HW] = w2;
    }
    __syncthreads();

    // ---- phase 5: final = corr + w·cv ; write final + init_corr ----
    for (int idx = t; idx < CVC * 16; idx += 224) {        // 784 float4
        int k = idx >> 4, q = idx & 15;
        float4 corr4 = *(const float4*)&outS[k * 64 + q * 4];
        float4 a0 = *(const float4*)&cvS[(0 * CVC + k) * 64 + q * 4];
        float4 a1 = *(const float4*)&cvS[(1 * CVC + k) * 64 + q * 4];
        float4 a2 = *(const float4*)&cvS[(2 * CVC + k) * 64 + q * 4];
        float4 w0 = *(const float4*)&wsm[0 * 64 + q * 4];
        float4 w1 = *(const float4*)&wsm[1 * 64 + q * 4];
        float4 w2 = *(const float4*)&wsm[2 * 64 + q * 4];
        float4 fin;
        fin.x = corr4.x + fmaf(w0.x, a0.x, fmaf(w1.x, a1.x, w2.x * a2.x));
        fin.y = corr4.y + fmaf(w0.y, a0.y, fmaf(w1.y, a1.y, w2.y * a2.y));
        fin.z = corr4.z + fmaf(w0.z, a0.z, fmaf(w1.z, a1.z, w2.z * a2.z));
        fin.w = corr4.w + fmaf(w0.w, a0.w, fmaf(w1.w, a1.w, w2.w * a2.w));
        size_t off = ((size_t)(b * CVC + k) * Hh + h) * Wd + x0 + q * 4;
        *(float4*)&out[off]       = fin;
        *(float4*)&out[NC_ + off] = corr4;
    }
}

// ---------------- launch ----------------
extern "C" void kernel_launch(void* const* d_in, const int* in_sizes, int n_in,
                              void* d_out, int out_size)
{
    const float* feat_l1 = (const float*)d_in[0];
    const float* feat_r1 = (const float*)d_in[1];
    const float* cv0     = (const float*)d_in[2];
    const float* cv1     = (const float*)d_in[3];
    const float* cv2     = (const float*)d_in[4];
    const float* W_f1    = (const float*)d_in[5];
    const float* b_f1    = (const float*)d_in[6];
    const float* W_f2    = (const float*)d_in[7];
    const float* b_f2    = (const float*)d_in[8];
    const float* W_geo   = (const float*)d_in[9];
    const float* b_geo   = (const float*)d_in[10];
    const float* W_sel   = (const float*)d_in[11];
    const float* b_sel   = (const float*)d_in[12];
    float* out = (float*)d_out;

    prep_kernel<<<68, 256>>>(W_f1, W_f2, W_geo, b_geo, W_sel, b_sel);

    fmap_kernel<<<dim3(NPIX / FMP, 2), 256>>>(feat_l1, feat_r1, b_f1, b_f2);

    int cs_smem = (64 * 68 + 3 * CVC * 64 + 3 * 64) * (int)sizeof(float);  // ~54.5KB
    static int cs_set = 0;
    if (!cs_set) {
        cudaFuncSetAttribute(corrsel_kernel, cudaFuncAttributeMaxDynamicSharedMemorySize, cs_smem);
        cs_set = 1;
    }
    corrsel_kernel<<<Bn * Hh * (Wd / 64), 224, cs_smem>>>(cv0, cv1, cv2, out);
}